// round 5
// baseline (speedup 1.0000x reference)
#include <cuda_runtime.h>
#include <cuda_pipeline.h>

// ---------------- problem dims (fixed by the dataset) ----------------
#define BATCH   2
#define C_IN    256
#define HH      40
#define WW      40
#define CMID    64     // compressed channels
#define CK      100    // k2 * S^2 encoder output channels
#define KK      25     // k2
#define HPAD    44     // xT padded (halo 2)
#define CPH     42     // comp padded (halo 1)

typedef unsigned long long u64;

__device__ __forceinline__ u64 dup2f(float x) {
    u64 r; asm("mov.b64 %0,{%1,%1};" : "=l"(r) : "f"(x)); return r;
}
__device__ __forceinline__ void fma2(u64& d, u64 a, u64 b) {
    asm("fma.rn.f32x2 %0,%1,%2,%0;" : "+l"(d) : "l"(a), "l"(b));
}

// ---------------- scratch (zero-initialized at module load; halos stay 0) ----------------
__device__ __align__(16) float g_xT  [BATCH * HPAD * HPAD * C_IN];   // x NHWC, 2-px zero halo
__device__ __align__(16) float g_comp[BATCH * CPH  * CPH  * CMID];   // compressed NHWC, 1-px halo
__device__ __align__(16) float g_kern[BATCH * HH * WW * CK];         // encoder conv out, NHWC
__device__ __align__(16) float g_wt  [2 * 9 * CMID * 50];            // w_enc [half][tap][ci][50]
__device__ __align__(16) float g_wc  [C_IN * CMID];                  // w_comp transposed [c][o]

// ---------------- prep: weight transposes ----------------
__global__ void prep_kernel(const float* __restrict__ wcomp,
                            const float* __restrict__ wenc) {
    int i = blockIdx.x * 256 + threadIdx.x;
    if (i < C_IN * CMID) {                    // g_wc[c][o] = wcomp[o][c]
        int c = i >> 6, o = i & 63;
        g_wc[i] = wcomp[o * C_IN + c];
    }
    int j = i - C_IN * CMID;
    if (j >= 0 && j < 57600) {                // g_wt[h][tap][ci][ol] = wenc[50h+ol][ci][tap]
        int h   = j / 28800;
        int r   = j % 28800;
        int tap = r / 3200;
        int r2  = r % 3200;
        int ci  = r2 / 50;
        int ol  = r2 % 50;
        g_wt[j] = wenc[(50 * h + ol) * (CMID * 9) + ci * 9 + tap];
    }
}

// ---------------- stage A: 1x1 compress GEMM (blocks 0..199) + x transpose (200..599) ----
#define AW_STRIDE 68
#define AX_STRIDE 20

__global__ void __launch_bounds__(128) stageA_compress(const float* __restrict__ x) {
    __shared__ float sm[64 * AW_STRIDE + 64 * AX_STRIDE];
    const int t   = threadIdx.x;
    const int blk = blockIdx.x;

    if (blk < 200) {
        float* w_s = sm;                    // [c_local][o] stride 68
        float* x_s = sm + 64 * AW_STRIDE;   // [c_local][px] stride 20

        const int g = blk * 16;             // global pixel (incl batch), 16-aligned
        const int b = g / (HH * WW);
        const int p = g % (HH * WW);

        const int px = t & 15;
        const int o0 = (t >> 4) << 3;       // 8 consecutive outputs

        u64 acc0 = 0, acc1 = 0, acc2 = 0, acc3 = 0;

        for (int c0 = 0; c0 < C_IN; c0 += 64) {
            __syncthreads();
            #pragma unroll
            for (int r = 0; r < 8; r++) {
                int idx = t + r * 128;
                int row = idx >> 4, col4 = idx & 15;
                *(float4*)&w_s[row * AW_STRIDE + col4 * 4] =
                    *(const float4*)&g_wc[(c0 + row) * CMID + col4 * 4];
            }
            #pragma unroll
            for (int r = 0; r < 2; r++) {
                int idx = t + r * 128;
                int row = idx >> 2, col4 = idx & 3;
                *(float4*)&x_s[row * AX_STRIDE + col4 * 4] =
                    *(const float4*)&x[((size_t)(b * C_IN) + c0 + row) * (HH * WW) + p + col4 * 4];
            }
            __syncthreads();
            #pragma unroll 8
            for (int c = 0; c < 64; c++) {
                u64 xx = dup2f(x_s[c * AX_STRIDE + px]);
                ulonglong2 wA = *(const ulonglong2*)&w_s[c * AW_STRIDE + o0];
                ulonglong2 wB = *(const ulonglong2*)&w_s[c * AW_STRIDE + o0 + 4];
                fma2(acc0, xx, wA.x); fma2(acc1, xx, wA.y);
                fma2(acc2, xx, wB.x); fma2(acc3, xx, wB.y);
            }
        }

        const int pix = p + px;
        const int hs = pix / WW, ws = pix % WW;
        float* dst = &g_comp[((size_t)(b * CPH + hs + 1) * CPH + (ws + 1)) * CMID + o0];
        *(ulonglong2*)(dst)     = make_ulonglong2(acc0, acc1);
        *(ulonglong2*)(dst + 4) = make_ulonglong2(acc2, acc3);
    } else {
        // x transpose: 32 px x 64 ch tile through smem
        float* s = sm;                      // [64][33]
        const int tb = blk - 200;
        const int pg = (tb % 100) * 32;
        const int c0 = (tb / 100) * 64;
        const int b  = pg / (HH * WW);
        const int p0 = pg % (HH * WW);
        #pragma unroll
        for (int r = 0; r < 16; r++) {
            int idx = t + r * 128;
            int cl = idx >> 5, pl = idx & 31;
            s[cl * 33 + pl] = x[((size_t)(b * C_IN) + c0 + cl) * (HH * WW) + p0 + pl];
        }
        __syncthreads();
        #pragma unroll
        for (int r = 0; r < 16; r++) {
            int idx = t + r * 128;
            int pl = idx >> 6, cl = idx & 63;
            int px = p0 + pl;
            int hs = px / WW, ws = px % WW;
            g_xT[((size_t)(b * HPAD + hs + 2) * HPAD + (ws + 2)) * C_IN + c0 + cl] =
                s[cl * 33 + pl];
        }
    }
}

// ---------------- stage B: 3x3 encoder conv (64 -> 100 ch), sync-free mainloop ----------
// 320 blocks = b(2) x ohalf(2) x rowpair(20) x colseg(4); 128 threads.
// Block: 20 px (2 rows x 10 cols) x 50 outputs. ALL 9 taps of the half's weights in smem.
// Thread (og = t/5: 2 packed outputs, cp = t%5: 2x2 px) -> 4 u64 accumulators.
#define W_HALF    28800                     // 9*64*50 floats
#define CS_STRIDE 66
#define COMP_TILE (48 * CS_STRIDE)
#define SMEM_B_BYTES ((W_HALF + COMP_TILE) * (int)sizeof(float))

__global__ void __launch_bounds__(128) stageB_encoder() {
    extern __shared__ float smB[];
    float* w_s    = smB;                    // [9][64][50]
    float* comp_s = smB + W_HALF;           // [48 px][66]

    const int t    = threadIdx.x;
    const int blk  = blockIdx.x;
    const int b    = blk / 160;
    const int rem  = blk % 160;
    const int h    = rem / 80;              // output-channel half
    const int rem2 = rem % 80;
    const int r0   = (rem2 / 4) * 2;        // output rows r0, r0+1
    const int cs0  = (rem2 % 4) * 10;       // output cols cs0..cs0+9

    // comp tile: padded rows r0..r0+3, padded cols cs0..cs0+11 (8B cp.async chunks)
    for (int i = t; i < 1536; i += 128) {
        int px = i >> 5, c2 = i & 31;
        int dr = px / 12, dc = px % 12;
        __pipeline_memcpy_async(
            &comp_s[px * CS_STRIDE + c2 * 2],
            &g_comp[((size_t)(b * CPH + r0 + dr) * CPH + cs0 + dc) * CMID + c2 * 2], 8);
    }
    // weights: contiguous 115.2 KB half, 16B chunks
    {
        const float4* wsrc = (const float4*)&g_wt[h * W_HALF];
        float4* wdst = (float4*)w_s;
        for (int i = t; i < W_HALF / 4; i += 128)
            __pipeline_memcpy_async(&wdst[i], &wsrc[i], 16);
    }
    __pipeline_commit();
    __pipeline_wait_prior(0);
    __syncthreads();

    const int og = t / 5;                   // 0..25 (active < 25)
    const int cp = t % 5;
    if (og < 25) {
        u64 a00 = 0, a01 = 0, a10 = 0, a11 = 0;
        const float* wt0 = &w_s[og * 2];
        #pragma unroll
        for (int tap = 0; tap < 9; tap++) {
            const float* xb = &comp_s[((tap / 3) * 12 + 2 * cp + (tap % 3)) * CS_STRIDE];
            const float* wt = wt0 + tap * 3200;
            #pragma unroll 4
            for (int ci = 0; ci < CMID; ci += 2) {
                float2 x00 = *(const float2*)&xb[ci];
                float2 x01 = *(const float2*)&xb[CS_STRIDE + ci];
                float2 x10 = *(const float2*)&xb[12 * CS_STRIDE + ci];
                float2 x11 = *(const float2*)&xb[13 * CS_STRIDE + ci];
                u64 w0 = *(const u64*)&wt[ci * 50];
                u64 w1 = *(const u64*)&wt[ci * 50 + 50];
                fma2(a00, dup2f(x00.x), w0); fma2(a01, dup2f(x01.x), w0);
                fma2(a10, dup2f(x10.x), w0); fma2(a11, dup2f(x11.x), w0);
                fma2(a00, dup2f(x00.y), w1); fma2(a01, dup2f(x01.y), w1);
                fma2(a10, dup2f(x10.y), w1); fma2(a11, dup2f(x11.y), w1);
            }
        }
        const int oc = h * 50 + og * 2;
        const int c0 = cs0 + 2 * cp;
        float* d00 = &g_kern[((size_t)(b * HH + r0) * WW + c0) * CK + oc];
        *(u64*)d00        = a00;
        *(u64*)(d00 + CK) = a01;
        float* d10 = d00 + WW * CK;
        *(u64*)d10        = a10;
        *(u64*)(d10 + CK) = a11;
    }
}

// ---------------- stage C: pixel-shuffle + softmax + reassembly ----------------
// 1600 blocks x 512 threads: 2 src pixels per block, 1 channel per thread.
__global__ void __launch_bounds__(512) stageC_reassemble(float* __restrict__ out) {
    __shared__ float4 sk[2][KK];

    const int t   = threadIdx.x;
    const int blk = blockIdx.x;
    const int b   = blk / 800;
    const int q   = blk % 800;

    const int wid = t >> 5, lane = t & 31;
    if (wid < 8) {   // 8 warps = 2 pixels x 4 subpixels
        const int px = wid >> 2, d = wid & 3;
        const int p  = 2 * q + px;
        const int hu = p / 20, pm20 = p % 20;
        const int hc = hu >> 1, sh = hu & 1;
        const int wc = 2 * pm20 + (d >> 1), sw = d & 1;
        float v = -3.0e38f;
        if (lane < KK)
            v = g_kern[((size_t)(b * HH + hc) * WW + wc) * CK + lane * 4 + sh * 2 + sw];
        float m = v;
        #pragma unroll
        for (int off = 16; off; off >>= 1)
            m = fmaxf(m, __shfl_xor_sync(0xffffffffu, m, off));
        float e = (lane < KK) ? __expf(v - m) : 0.f;
        float s = e;
        #pragma unroll
        for (int off = 16; off; off >>= 1)
            s += __shfl_xor_sync(0xffffffffu, s, off);
        if (lane < KK)
            ((float*)&sk[px][lane])[d] = e / s;
    }
    __syncthreads();

    const int half = t >> 8;
    const int ch   = t & 255;
    const int p    = 2 * q + half;
    const int hsrc = p / WW, wsrc = p % WW;
    const int hu   = p / 20;
    const int wu0  = (p % 20) * 4;

    const float* xb = &g_xT[((size_t)(b * HPAD + hsrc) * HPAD + wsrc) * C_IN + ch];
    const ulonglong2* skp = (const ulonglong2*)&sk[half][0];

    u64 a01 = 0, a23 = 0;
    #pragma unroll
    for (int ki = 0; ki < 5; ki++) {
        float xr[5];
        #pragma unroll
        for (int kj = 0; kj < 5; kj++)
            xr[kj] = xb[(ki * HPAD + kj) * C_IN];
        #pragma unroll
        for (int kj = 0; kj < 5; kj++) {
            ulonglong2 w = skp[ki * 5 + kj];
            u64 xx = dup2f(xr[kj]);
            fma2(a01, xx, w.x);
            fma2(a23, xx, w.y);
        }
    }
    float* dst = out + ((size_t)(b * C_IN + ch) * (2 * HH) + hu) * (2 * WW) + wu0;
    *(ulonglong2*)dst = make_ulonglong2(a01, a23);
}

// ---------------- launch ----------------
extern "C" void kernel_launch(void* const* d_in, const int* in_sizes, int n_in,
                              void* d_out, int out_size) {
    const float* x     = (const float*)d_in[0];
    const float* wcomp = (const float*)d_in[1];
    const float* wenc  = (const float*)d_in[2];
    float* out = (float*)d_out;

    cudaFuncSetAttribute(stageB_encoder,
                         cudaFuncAttributeMaxDynamicSharedMemorySize, SMEM_B_BYTES);

    prep_kernel<<<(C_IN * CMID + 57600 + 255) / 256, 256>>>(wcomp, wenc);
    stageA_compress<<<600, 128>>>(x);
    stageB_encoder<<<320, 128, SMEM_B_BYTES>>>();
    stageC_reassemble<<<BATCH * 800, 512>>>(out);
}

// round 6
// speedup vs baseline: 1.0684x; 1.0684x over previous
#include <cuda_runtime.h>

// ---------------- problem dims (fixed by the dataset) ----------------
#define BATCH   2
#define C_IN    256
#define HH      40
#define WW      40
#define CMID    64     // compressed channels
#define CK      100    // k2 * S^2 encoder output channels
#define KK      25     // k2
#define HPAD    44     // xT padded (halo 2)
#define CPH     42     // comp padded (halo 1)

typedef unsigned long long u64;

__device__ __forceinline__ u64 dup2f(float x) {
    u64 r; asm("mov.b64 %0,{%1,%1};" : "=l"(r) : "f"(x)); return r;
}
__device__ __forceinline__ void fma2(u64& d, u64 a, u64 b) {
    asm("fma.rn.f32x2 %0,%1,%2,%0;" : "+l"(d) : "l"(a), "l"(b));
}

// ---------------- scratch (zero-initialized at module load; halos stay 0) ----------------
__device__ __align__(16) float g_xT  [BATCH * HPAD * HPAD * C_IN];   // x NHWC, 2-px zero halo
__device__ __align__(16) float g_comp[BATCH * CPH  * CPH  * CMID];   // compressed NHWC, 1-px halo
__device__ __align__(16) float g_kern[BATCH * HH * WW * CK];         // encoder conv out, NHWC
__device__ __align__(16) float g_wt  [2 * 9 * CMID * 50];            // w_enc [half][tap][ci][50]
__device__ __align__(16) float g_wc  [C_IN * CMID];                  // w_comp transposed [c][o]

// ---------------- prepx: x transpose (blocks 0..399) + weight transposes ----------------
__global__ void __launch_bounds__(128) prepx_kernel(const float* __restrict__ x,
                                                    const float* __restrict__ wcomp,
                                                    const float* __restrict__ wenc) {
    const int t   = threadIdx.x;
    const int blk = blockIdx.x;

    if (blk < 400) {                          // x transpose: 32 px x 64 ch tile through smem
        __shared__ float s[64 * 33];
        const int pg = (blk % 100) * 32;
        const int c0 = (blk / 100) * 64;
        const int b  = pg / (HH * WW);
        const int p0 = pg % (HH * WW);
        #pragma unroll
        for (int r = 0; r < 16; r++) {
            int idx = t + r * 128;
            int cl = idx >> 5, pl = idx & 31;
            s[cl * 33 + pl] = x[((size_t)(b * C_IN) + c0 + cl) * (HH * WW) + p0 + pl];
        }
        __syncthreads();
        #pragma unroll
        for (int r = 0; r < 16; r++) {
            int idx = t + r * 128;
            int pl = idx >> 6, cl = idx & 63;
            int px = p0 + pl;
            int hs = px / WW, ws = px % WW;
            g_xT[((size_t)(b * HPAD + hs + 2) * HPAD + (ws + 2)) * C_IN + c0 + cl] =
                s[cl * 33 + pl];
        }
        return;
    }
    int i = (blk - 400) * 128 + t;
    if (i < C_IN * CMID) {                    // g_wc[c][o] = wcomp[o][c]
        int c = i >> 6, o = i & 63;
        g_wc[i] = wcomp[o * C_IN + c];
    }
    int j = i - C_IN * CMID;
    if (j >= 0 && j < 57600) {                // g_wt[h][tap][ci][ol] = wenc[50h+ol][ci][tap]
        int h   = j / 28800;
        int r   = j % 28800;
        int tap = r / 3200;
        int r2  = r % 3200;
        int ci  = r2 / 50;
        int ol  = r2 % 50;
        g_wt[j] = wenc[(50 * h + ol) * (CMID * 9) + ci * 9 + tap];
    }
}

// ---------------- stage A: 1x1 compress GEMM ----------------
// 200 blocks x 128 threads. Block = 16 px x 64 outputs, K chunked by 64.
#define AW_STRIDE 68
#define AX_STRIDE 20

__global__ void __launch_bounds__(128) stageA_compress(const float* __restrict__ x) {
    __shared__ float w_s[64 * AW_STRIDE];
    __shared__ float x_s[64 * AX_STRIDE];

    const int t = threadIdx.x;
    const int g = blockIdx.x * 16;          // global pixel (incl batch), 16-aligned
    const int b = g / (HH * WW);
    const int p = g % (HH * WW);

    const int px = t & 15;
    const int o0 = (t >> 4) << 3;           // 8 consecutive outputs

    u64 acc0 = 0, acc1 = 0, acc2 = 0, acc3 = 0;

    for (int c0 = 0; c0 < C_IN; c0 += 64) {
        __syncthreads();
        #pragma unroll
        for (int r = 0; r < 8; r++) {
            int idx = t + r * 128;
            int row = idx >> 4, col4 = idx & 15;
            *(float4*)&w_s[row * AW_STRIDE + col4 * 4] =
                *(const float4*)&g_wc[(c0 + row) * CMID + col4 * 4];
        }
        #pragma unroll
        for (int r = 0; r < 2; r++) {
            int idx = t + r * 128;
            int row = idx >> 2, col4 = idx & 3;
            *(float4*)&x_s[row * AX_STRIDE + col4 * 4] =
                *(const float4*)&x[((size_t)(b * C_IN) + c0 + row) * (HH * WW) + p + col4 * 4];
        }
        __syncthreads();
        #pragma unroll 8
        for (int c = 0; c < 64; c++) {
            u64 xx = dup2f(x_s[c * AX_STRIDE + px]);
            ulonglong2 wA = *(const ulonglong2*)&w_s[c * AW_STRIDE + o0];
            ulonglong2 wB = *(const ulonglong2*)&w_s[c * AW_STRIDE + o0 + 4];
            fma2(acc0, xx, wA.x); fma2(acc1, xx, wA.y);
            fma2(acc2, xx, wB.x); fma2(acc3, xx, wB.y);
        }
    }

    const int pix = p + px;
    const int hs = pix / WW, ws = pix % WW;
    float* dst = &g_comp[((size_t)(b * CPH + hs + 1) * CPH + (ws + 1)) * CMID + o0];
    *(ulonglong2*)(dst)     = make_ulonglong2(acc0, acc1);
    *(ulonglong2*)(dst + 4) = make_ulonglong2(acc2, acc3);
}

// ---------------- stage B: 3x3 encoder conv (64 -> 100 ch) ----------------
// 320 blocks = b(2) x ohalf(2) x rowpair(20) x colseg(4); 128 threads.
// comp tile in smem (12.7KB); weights streamed from L2 via unrolled LDG.
#define W_HALF    28800                     // 9*64*50 floats
#define CS_STRIDE 66

__global__ void __launch_bounds__(128) stageB_encoder() {
    __shared__ float comp_s[48 * CS_STRIDE];

    const int t    = threadIdx.x;
    const int blk  = blockIdx.x;
    const int b    = blk / 160;
    const int rem  = blk % 160;
    const int h    = rem / 80;              // output-channel half
    const int rem2 = rem % 80;
    const int r0   = (rem2 / 4) * 2;        // output rows r0, r0+1
    const int cs0  = (rem2 % 4) * 10;       // output cols cs0..cs0+9

    // comp tile: padded rows r0..r0+3, cols cs0..cs0+11 (warp = one px's 64ch, coalesced)
    #pragma unroll
    for (int r = 0; r < 12; r++) {
        int i  = t + r * 128;
        int px = i >> 5, c2 = i & 31;
        int dr = px / 12, dc = px % 12;
        *(float2*)&comp_s[px * CS_STRIDE + c2 * 2] =
            *(const float2*)&g_comp[((size_t)(b * CPH + r0 + dr) * CPH + cs0 + dc) * CMID + c2 * 2];
    }
    __syncthreads();

    const int og = t / 5;                   // 0..25 (active < 25)
    const int cp = t % 5;
    if (og >= 25) return;

    u64 a00 = 0, a01 = 0, a10 = 0, a11 = 0;
    const float* wt0 = &g_wt[h * W_HALF + og * 2];
    #pragma unroll
    for (int tap = 0; tap < 9; tap++) {
        const float* xb = &comp_s[((tap / 3) * 12 + 2 * cp + (tap % 3)) * CS_STRIDE];
        const float* wt = wt0 + tap * 3200;
        #pragma unroll 8
        for (int ci = 0; ci < CMID; ci += 2) {
            float2 x00 = *(const float2*)&xb[ci];
            float2 x01 = *(const float2*)&xb[CS_STRIDE + ci];
            float2 x10 = *(const float2*)&xb[12 * CS_STRIDE + ci];
            float2 x11 = *(const float2*)&xb[13 * CS_STRIDE + ci];
            u64 w0 = *(const u64*)&wt[ci * 50];
            u64 w1 = *(const u64*)&wt[ci * 50 + 50];
            fma2(a00, dup2f(x00.x), w0); fma2(a01, dup2f(x01.x), w0);
            fma2(a10, dup2f(x10.x), w0); fma2(a11, dup2f(x11.x), w0);
            fma2(a00, dup2f(x00.y), w1); fma2(a01, dup2f(x01.y), w1);
            fma2(a10, dup2f(x10.y), w1); fma2(a11, dup2f(x11.y), w1);
        }
    }
    const int oc = h * 50 + og * 2;
    const int c0 = cs0 + 2 * cp;
    float* d00 = &g_kern[((size_t)(b * HH + r0) * WW + c0) * CK + oc];
    *(u64*)d00        = a00;
    *(u64*)(d00 + CK) = a01;
    float* d10 = d00 + WW * CK;
    *(u64*)d10        = a10;
    *(u64*)(d10 + CK) = a11;
}

// ---------------- stage C: pixel-shuffle + softmax + reassembly ----------------
// 3200 blocks x 256 threads: 1 src pixel per block, 1 channel per thread.
// All 25 x-loads issued up-front (MLP=25) -> single latency wave.
__global__ void __launch_bounds__(256) stageC_reassemble(float* __restrict__ out) {
    __shared__ float4 sk[KK];

    const int t   = threadIdx.x;
    const int blk = blockIdx.x;
    const int b   = blk / (HH * WW);
    const int p   = blk % (HH * WW);

    const int hsrc = p / WW, wsrc = p % WW;
    const int hu   = p / 20;
    const int pm20 = p % 20;
    const int wu0  = pm20 * 4;

    const int wid = t >> 5, lane = t & 31;

    // start the 25 x-loads immediately (independent of softmax)
    const float* xb = &g_xT[((size_t)(b * HPAD + hsrc) * HPAD + wsrc) * C_IN + t];
    float xr[25];
    #pragma unroll
    for (int i = 0; i < 25; i++)
        xr[i] = xb[((i / 5) * HPAD + (i % 5)) * C_IN];

    if (wid < 4) {   // 4 warps = 4 subpixels
        const int d  = wid;
        const int hc = hu >> 1, sh = hu & 1;
        const int wc = 2 * pm20 + (d >> 1), sw = d & 1;
        float v = -3.0e38f;
        if (lane < KK)
            v = g_kern[((size_t)(b * HH + hc) * WW + wc) * CK + lane * 4 + sh * 2 + sw];
        float m = v;
        #pragma unroll
        for (int off = 16; off; off >>= 1)
            m = fmaxf(m, __shfl_xor_sync(0xffffffffu, m, off));
        float e = (lane < KK) ? __expf(v - m) : 0.f;
        float s = e;
        #pragma unroll
        for (int off = 16; off; off >>= 1)
            s += __shfl_xor_sync(0xffffffffu, s, off);
        if (lane < KK)
            ((float*)&sk[lane])[d] = e / s;
    }
    __syncthreads();

    const ulonglong2* skp = (const ulonglong2*)&sk[0];
    u64 a01 = 0, a23 = 0;
    #pragma unroll
    for (int i = 0; i < 25; i++) {
        ulonglong2 w = skp[i];
        u64 xx = dup2f(xr[i]);
        fma2(a01, xx, w.x);
        fma2(a23, xx, w.y);
    }
    float* dst = out + ((size_t)(b * C_IN + t) * (2 * HH) + hu) * (2 * WW) + wu0;
    *(ulonglong2*)dst = make_ulonglong2(a01, a23);
}

// ---------------- launch ----------------
extern "C" void kernel_launch(void* const* d_in, const int* in_sizes, int n_in,
                              void* d_out, int out_size) {
    const float* x     = (const float*)d_in[0];
    const float* wcomp = (const float*)d_in[1];
    const float* wenc  = (const float*)d_in[2];
    float* out = (float*)d_out;

    prepx_kernel<<<400 + (C_IN * CMID + 57600 + 127) / 128, 128>>>(x, wcomp, wenc);
    stageA_compress<<<200, 128>>>(x);
    stageB_encoder<<<320, 128>>>();
    stageC_reassemble<<<BATCH * HH * WW, 256>>>(out);
}